// round 14
// baseline (speedup 1.0000x reference)
#include <cuda_runtime.h>
#include <cuda_bf16.h>

#define BB 8
#define NN 32768
#define CC 32
#define KIN 22

constexpr int THREADS = 512;  // 16 warps = 2 halves x 8 warps
constexpr int TE = 256;
constexpr int P = 128;        // points per CTA (64 per half)

// ---------------- device scratch ----------------
__device__ unsigned g_f2h[(size_t)BB * 128 * (NN / 2)];
__device__ unsigned g_f2l[(size_t)BB * 128 * (NN / 2)];
__device__ int   g_cf[2 * BB * CC * 128];
__device__ int   g_cc[2 * BB * CC * 32];
__device__ float g_cf2[2 * BB * CC * 128];
__device__ int   g_net[BB * 128];

// weight fragments (u32 = 2 packed bf16): per (mt,ks): 64 uint4 = hi(32)+lo(32)
__device__ unsigned fr_in [256 * 32];
__device__ unsigned fr_w1 [2][64 * 256];
__device__ unsigned fr_w2 [2][128 * 64];
__device__ unsigned fr_w3 [2][128 * 128];
__device__ unsigned fr_c1 [2][128 * 128];
__device__ unsigned fr_c2 [2][256 * 128];
__device__ unsigned fr_c3 [2][32 * 256];
__device__ unsigned fr_o1 [128 * 256];
__device__ unsigned fr_o2 [128 * 128];

// ---------------- prep: pack all weights into MMA fragment layout ------------
struct FJobs {
    const float* src[15];
    unsigned*    dst[15];
    int Ireal[15], Ipad[15], O[15], n[15];
};

__global__ void frag_all(FJobs jobs, int total) {
    int t = blockIdx.x * blockDim.x + threadIdx.x;
    if (t >= total) return;
    int j = 0, e = t;
    while (e >= jobs.n[j]) { e -= jobs.n[j]; j++; }
    int Ireal = jobs.Ireal[j], Ipad = jobs.Ipad[j];
    int KS = Ipad / 16;
    int f = e >> 7;
    int idx = e & 127;
    int lane = idx >> 2, r = idx & 3;
    int term = f & 1, q = f >> 1;
    int ks = q % KS, mt = q / KS;
    int g = lane >> 2, c = lane & 3;
    int row = mt * 16 + g + (r & 1) * 8;
    int k0  = ks * 16 + 2 * c + (r & 2) * 4;
    const float* W = jobs.src[j];
    float v0 = (k0     < Ireal) ? W[row * Ireal + k0]     : 0.0f;
    float v1 = (k0 + 1 < Ireal) ? W[row * Ireal + k0 + 1] : 0.0f;
    unsigned short h0, h1;
    if (term == 0) {
        h0 = __bfloat16_as_ushort(__float2bfloat16(v0));
        h1 = __bfloat16_as_ushort(__float2bfloat16(v1));
    } else {
        __nv_bfloat16 b0 = __float2bfloat16(v0);
        __nv_bfloat16 b1 = __float2bfloat16(v1);
        h0 = __bfloat16_as_ushort(__float2bfloat16(v0 - __bfloat162float(b0)));
        h1 = __bfloat16_as_ushort(__float2bfloat16(v1 - __bfloat162float(b1)));
    }
    jobs.dst[j][e] = (unsigned)h0 | ((unsigned)h1 << 16);
}

__global__ void zero1_k() {
    int t = blockIdx.x * blockDim.x + threadIdx.x;
    if (t < 2 * BB * CC * 128) g_cf[t] = 0;
    if (t < 2 * BB * CC * 32)  g_cc[t] = 0;
}
__global__ void zero2_k() {
    int t = blockIdx.x * blockDim.x + threadIdx.x;
    if (t < BB * 128) g_net[t] = 0;
}

// ---------------- asm helpers ----------------
__device__ __forceinline__ unsigned sptr(const void* p) {
    return (unsigned)__cvta_generic_to_shared(p);
}
__device__ __forceinline__ void barh(int h) {
    asm volatile("bar.sync %0, %1;" :: "r"(h + 1), "r"(256) : "memory");
}
__device__ __forceinline__ void mma16816(float* d, unsigned a0, unsigned a1,
                                         unsigned a2, unsigned a3,
                                         unsigned b0, unsigned b1) {
    asm volatile(
        "mma.sync.aligned.m16n8k16.row.col.f32.bf16.bf16.f32 "
        "{%0,%1,%2,%3}, {%4,%5,%6,%7}, {%8,%9}, {%0,%1,%2,%3};"
        : "+f"(d[0]), "+f"(d[1]), "+f"(d[2]), "+f"(d[3])
        : "r"(a0), "r"(a1), "r"(a2), "r"(a3), "r"(b0), "r"(b1));
}
__device__ __forceinline__ void ldsm_x4_t(unsigned addr, unsigned* r) {
    asm volatile("ldmatrix.sync.aligned.m8n8.x4.trans.shared.b16 {%0,%1,%2,%3}, [%4];"
                 : "=r"(r[0]), "=r"(r[1]), "=r"(r[2]), "=r"(r[3]) : "r"(addr));
}
__device__ __forceinline__ void stsm_x2(unsigned addr, unsigned r0, unsigned r1) {
    asm volatile("stmatrix.sync.aligned.m8n8.x2.shared.b16 [%0], {%1,%2};"
                 :: "r"(addr), "r"(r0), "r"(r1));
}
__device__ __forceinline__ unsigned pack_bf(__nv_bfloat16 a, __nv_bfloat16 b) {
    return (unsigned)__bfloat16_as_ushort(a) | ((unsigned)__bfloat16_as_ushort(b) << 16);
}
__device__ __forceinline__ float bflo(unsigned u) {
    return __bfloat162float(__ushort_as_bfloat16((unsigned short)(u & 0xFFFF)));
}
__device__ __forceinline__ float bfhi(unsigned u) {
    return __bfloat162float(__ushort_as_bfloat16((unsigned short)(u >> 16)));
}
__device__ __forceinline__ void split2(float v0, float v1, unsigned& hw, unsigned& lw) {
    __nv_bfloat16 h0 = __float2bfloat16(v0), h1 = __float2bfloat16(v1);
    hw = pack_bf(h0, h1);
    lw = pack_bf(__float2bfloat16(v0 - __bfloat162float(h0)),
                 __float2bfloat16(v1 - __bfloat162float(h1)));
}
// swizzled element offset: row = channel, 256B row, XOR-16B swizzle (within 128B half)
__device__ __forceinline__ int soff(int c, int q) {   // q = point pair index (u32)
    return c * 256 + ((q * 4) ^ ((c & 7) << 4));
}

// ---------------- per-half tensor-core layer: D[O x 64] = W[O x K] * H[K x 64]
// 8 warps per half; warp grid (MT/WM) x (8/WN) == 8; hoff = half byte offset (0/128)
// Weight prefetch enabled only for WM<=2 (register budget).
template <int K, int O, int WM, int WN, bool RELU>
__device__ __forceinline__ void layerMMA(const unsigned* __restrict__ WF,
                                         const float* __restrict__ bias,
                                         const __nv_bfloat16* Shi, const __nv_bfloat16* Slo,
                                         __nv_bfloat16* Dhi, __nv_bfloat16* Dlo,
                                         int wh, int lane, unsigned hoff) {
    constexpr int KS = K / 16;
    constexpr int MT = O / 16;
    constexpr int GN = 8 / WN;
    constexpr bool PF = (WM <= 2);
    static_assert((MT / WM) * GN == 8, "warp grid");
    static_assert(WN >= 2, "x4 path only");
    int gm = wh / GN, gn = wh % GN;
    int g = lane >> 2;
    float acc[WM][WN][4];
#pragma unroll
    for (int i = 0; i < WM; i++) {
        int mr = (gm * WM + i) * 16 + g;
        float b0 = __ldg(bias + mr), b1 = __ldg(bias + mr + 8);
#pragma unroll
        for (int j = 0; j < WN; j++) {
            acc[i][j][0] = b0; acc[i][j][1] = b0;
            acc[i][j][2] = b1; acc[i][j][3] = b1;
        }
    }
    int krow = ((lane >> 3) & 1) * 8 + (lane & 7);
    unsigned swz = ((unsigned)(krow & 7)) << 4;
    int ntoff = lane >> 4;
    unsigned baseH = sptr(Shi) + krow * 256 + hoff;
    unsigned baseL = sptr(Slo) + krow * 256 + hoff;

    uint4 ahc[WM], alc[WM];
    if (PF) {
#pragma unroll
        for (int i = 0; i < WM; i++) {
            const uint4* bp = reinterpret_cast<const uint4*>(WF) + ((gm * WM + i) * KS) * 64 + lane;
            ahc[i] = __ldg(bp); alc[i] = __ldg(bp + 32);
        }
    }
#pragma unroll
    for (int ks = 0; ks < KS; ks++) {
        uint4 ahn[WM], aln[WM];
        if (PF) {
            if (ks + 1 < KS) {
#pragma unroll
                for (int i = 0; i < WM; i++) {
                    const uint4* bp = reinterpret_cast<const uint4*>(WF) + ((gm * WM + i) * KS + ks + 1) * 64 + lane;
                    ahn[i] = __ldg(bp); aln[i] = __ldg(bp + 32);
                }
            }
        } else {
#pragma unroll
            for (int i = 0; i < WM; i++) {
                const uint4* bp = reinterpret_cast<const uint4*>(WF) + ((gm * WM + i) * KS + ks) * 64 + lane;
                ahc[i] = __ldg(bp); alc[i] = __ldg(bp + 32);
            }
        }
        unsigned koff = (unsigned)ks * 4096;
        constexpr int NP = WN / 2;
        unsigned bh[NP][4], bl[NP][4];
#pragma unroll
        for (int jp = 0; jp < NP; jp++) {
            unsigned col = ((unsigned)((gn * WN + 2 * jp + ntoff) * 16)) ^ swz;
            ldsm_x4_t(baseH + koff + col, bh[jp]);
            ldsm_x4_t(baseL + koff + col, bl[jp]);
        }
#pragma unroll
        for (int jp = 0; jp < NP; jp++)
#pragma unroll
            for (int i = 0; i < WM; i++) {
                mma16816(acc[i][2 * jp],     ahc[i].x, ahc[i].y, ahc[i].z, ahc[i].w, bh[jp][0], bh[jp][1]);
                mma16816(acc[i][2 * jp],     ahc[i].x, ahc[i].y, ahc[i].z, ahc[i].w, bl[jp][0], bl[jp][1]);
                mma16816(acc[i][2 * jp],     alc[i].x, alc[i].y, alc[i].z, alc[i].w, bh[jp][0], bh[jp][1]);
                mma16816(acc[i][2 * jp + 1], ahc[i].x, ahc[i].y, ahc[i].z, ahc[i].w, bh[jp][2], bh[jp][3]);
                mma16816(acc[i][2 * jp + 1], ahc[i].x, ahc[i].y, ahc[i].z, ahc[i].w, bl[jp][2], bl[jp][3]);
                mma16816(acc[i][2 * jp + 1], alc[i].x, alc[i].y, alc[i].z, alc[i].w, bh[jp][2], bh[jp][3]);
            }
        if (PF && ks + 1 < KS) {
#pragma unroll
            for (int i = 0; i < WM; i++) { ahc[i] = ahn[i]; alc[i] = aln[i]; }
        }
    }
    int sl = lane & 15;
#pragma unroll
    for (int i = 0; i < WM; i++) {
        int mrow = (gm * WM + i) * 16 + (sl >> 3) * 8 + (sl & 7);
        unsigned sswz = ((unsigned)(mrow & 7)) << 4;
        unsigned stH = sptr(Dhi) + mrow * 256 + hoff;
        unsigned stL = sptr(Dlo) + mrow * 256 + hoff;
#pragma unroll
        for (int j = 0; j < WN; j++) {
            unsigned col = ((unsigned)((gn * WN + j) * 16)) ^ sswz;
            float d0 = acc[i][j][0], d1 = acc[i][j][1], d2 = acc[i][j][2], d3 = acc[i][j][3];
            if (RELU) {
                d0 = fmaxf(d0, 0.f); d1 = fmaxf(d1, 0.f);
                d2 = fmaxf(d2, 0.f); d3 = fmaxf(d3, 0.f);
            }
            unsigned h01, l01, h23, l23;
            split2(d0, d1, h01, l01);
            split2(d2, d3, h23, l23);
            stsm_x2(stH + col, h01, h23);
            stsm_x2(stL + col, l01, l23);
        }
    }
}

// shared layout (bytes): A 256ch, B 128ch, rows = 256B swizzled
constexpr int AHI_OFF = 0;
constexpr int ALO_OFF = 65536;
constexpr int BHI_OFF = 131072;
constexpr int BLO_OFF = 163840;
constexpr int CFL_OFF = 196608;
constexpr int CCL_OFF = 212992;
constexpr int CL_OFF  = 217088;
constexpr int SMEM_BYTES = 218112;

// ---------------- kernel A ----------------
__global__ __launch_bounds__(THREADS, 1) void kA(const float* __restrict__ feat,
                                                 const int* __restrict__ clus,
                                                 const float* b_in, const float* b1,
                                                 const float* b2, const float* bc1,
                                                 const float* bc2, const float* bc3) {
    extern __shared__ char sm[];
    __nv_bfloat16* Ahi = (__nv_bfloat16*)(sm + AHI_OFF);
    __nv_bfloat16* Alo = (__nv_bfloat16*)(sm + ALO_OFF);
    __nv_bfloat16* Bhi = (__nv_bfloat16*)(sm + BHI_OFF);
    __nv_bfloat16* Blo = (__nv_bfloat16*)(sm + BLO_OFF);
    int* cfl = (int*)(sm + CFL_OFF);
    int* ccl = (int*)(sm + CCL_OFF);
    int* cl  = (int*)(sm + CL_OFF);
    int t = threadIdx.x, w = t >> 5, lane = t & 31;
    int h = w >> 3, wh = w & 7, t2 = t & 255;
    unsigned hoff = (unsigned)h * 128;
    int qb = h * 32;
    int b = blockIdx.x >> 8, nblk = blockIdx.x & 255;
    int n0 = nblk * P, q0 = nblk * (P / 2);

    for (int r = t; r < CC * 128; r += THREADS) cfl[r] = 0;
    for (int r = t; r < CC * 32; r += THREADS)  ccl[r] = 0;
    if (t < P) cl[t] = clus[(size_t)b * NN + n0 + t];
    for (int r = t2; r < 32 * 32; r += 256) {               // features pad 22->32 (own half)
        int c = r >> 5, q = qb + (r & 31);
        float v0 = (c < KIN) ? feat[((size_t)b * NN + n0 + 2 * q) * KIN + c] : 0.0f;
        float v1 = (c < KIN) ? feat[((size_t)b * NN + n0 + 2 * q + 1) * KIN + c] : 0.0f;
        unsigned hw, lw; split2(v0, v1, hw, lw);
        *(unsigned*)((char*)Bhi + soff(c, q)) = hw;
        *(unsigned*)((char*)Blo + soff(c, q)) = lw;
    }
    __syncthreads();
    layerMMA<32, 256, 4, 4, true>(fr_in, b_in, Bhi, Blo, Ahi, Alo, wh, lane, hoff);
    barh(h);
    layerMMA<256, 64, 2, 2, true>(fr_w1[0], b1, Ahi, Alo, Bhi, Blo, wh, lane, hoff);
    barh(h);
    layerMMA<64, 128, 4, 2, true>(fr_w2[0], b2, Bhi, Blo, Ahi, Alo, wh, lane, hoff);
    barh(h);
    for (int r = t2; r < 128 * 32; r += 256) {              // f2 store + segmax cf (own half)
        int c = r >> 5, q = qb + (r & 31);
        unsigned h2 = *(unsigned*)((char*)Ahi + soff(c, q));
        unsigned l2 = *(unsigned*)((char*)Alo + soff(c, q));
        size_t gi = ((size_t)(b * 128 + c)) * (NN / 2) + q0 + q;
        g_f2h[gi] = h2; g_f2l[gi] = l2;
        atomicMax(&cfl[cl[2 * q] * 128 + c], __float_as_int(bflo(h2) + bflo(l2)));
        atomicMax(&cfl[cl[2 * q + 1] * 128 + c], __float_as_int(bfhi(h2) + bfhi(l2)));
    }
    layerMMA<128, 128, 4, 2, true>(fr_c1[0], bc1, Ahi, Alo, Bhi, Blo, wh, lane, hoff);
    barh(h);
    layerMMA<128, 256, 4, 4, true>(fr_c2[0], bc2, Bhi, Blo, Ahi, Alo, wh, lane, hoff);
    barh(h);
    layerMMA<256, 32, 1, 2, true>(fr_c3[0], bc3, Ahi, Alo, Bhi, Blo, wh, lane, hoff);
    barh(h);
    for (int r = t2; r < 32 * 32; r += 256) {               // segmax cc (own half)
        int c = r >> 5, q = qb + (r & 31);
        unsigned h2 = *(unsigned*)((char*)Bhi + soff(c, q));
        unsigned l2 = *(unsigned*)((char*)Blo + soff(c, q));
        atomicMax(&ccl[cl[2 * q] * 32 + c], __float_as_int(bflo(h2) + bflo(l2)));
        atomicMax(&ccl[cl[2 * q + 1] * 32 + c], __float_as_int(bfhi(h2) + bfhi(l2)));
    }
    __syncthreads();
    for (int r = t; r < CC * 128; r += THREADS) { int v = cfl[r]; if (v) atomicMax(&g_cf[b * CC * 128 + r], v); }
    for (int r = t; r < CC * 32; r += THREADS)  { int v = ccl[r]; if (v) atomicMax(&g_cc[b * CC * 32 + r], v); }
}

// ---------------- kernel B: per-batch corr matrix + cf @ corr ----------------
__global__ void kB(int it) {
    __shared__ float cm[CC * 32], corr[CC * CC], invn[CC], cfs[CC * 128];
    int b = blockIdx.x, t = threadIdx.x;
    for (int r = t; r < CC * 32; r += TE)  cm[r]  = __int_as_float(g_cc[(it * BB + b) * CC * 32 + r]);
    for (int r = t; r < CC * 128; r += TE) cfs[r] = __int_as_float(g_cf[(it * BB + b) * CC * 128 + r]);
    __syncthreads();
    if (t < CC) {
        float ss = 0.f;
        for (int c = 0; c < 32; c++) { float v = cm[t * 32 + c]; ss += v * v; }
        invn[t] = 1.0f / fmaxf(sqrtf(ss), 1e-12f);
    }
    __syncthreads();
    for (int r = t; r < CC * 32; r += TE) cm[r] *= invn[r >> 5];
    __syncthreads();
    for (int r = t; r < CC * CC; r += TE) {
        int c1 = r >> 5, c2 = r & 31;
        float ss = 0.f;
        for (int c = 0; c < 32; c++) ss += cm[c1 * 32 + c] * cm[c2 * 32 + c];
        corr[r] = ss;
    }
    __syncthreads();
    for (int r = t; r < CC * 128; r += TE) {
        int c2 = r >> 7, ch = r & 127;
        float ss = 0.f;
        for (int c1 = 0; c1 < 32; c1++) ss += cfs[c1 * 128 + ch] * corr[c1 * 32 + c2];
        g_cf2[(it * BB + b) * CC * 128 + r] = ss;
    }
}

// ---------------- kernel C ----------------
__global__ __launch_bounds__(THREADS, 1) void kC(const int* __restrict__ clus,
                                                 const float* b3, const float* b1,
                                                 const float* b2, const float* bc1,
                                                 const float* bc2, const float* bc3) {
    extern __shared__ char sm[];
    __nv_bfloat16* Ahi = (__nv_bfloat16*)(sm + AHI_OFF);
    __nv_bfloat16* Alo = (__nv_bfloat16*)(sm + ALO_OFF);
    __nv_bfloat16* Bhi = (__nv_bfloat16*)(sm + BHI_OFF);
    __nv_bfloat16* Blo = (__nv_bfloat16*)(sm + BLO_OFF);
    int* cfl = (int*)(sm + CFL_OFF);
    int* ccl = (int*)(sm + CCL_OFF);
    int* cl0 = (int*)(sm + CL_OFF);
    int* cl1 = cl0 + 128;
    int t = threadIdx.x, w = t >> 5, lane = t & 31;
    int h = w >> 3, wh = w & 7, t2 = t & 255;
    unsigned hoff = (unsigned)h * 128;
    int qb = h * 32;
    int b = blockIdx.x >> 8, nblk = blockIdx.x & 255;
    int n0 = nblk * P, q0 = nblk * (P / 2);

    for (int r = t; r < CC * 128; r += THREADS) cfl[r] = 0;
    for (int r = t; r < CC * 32; r += THREADS)  ccl[r] = 0;
    if (t < P) {
        cl0[t] = clus[(size_t)b * NN + n0 + t];
        cl1[t] = clus[(size_t)(BB + b) * NN + n0 + t];
    }
    for (int r = t2; r < 128 * 32; r += 256) {              // load f2 -> B (own half)
        int c = r >> 5, q = qb + (r & 31);
        size_t gi = ((size_t)(b * 128 + c)) * (NN / 2) + q0 + q;
        *(unsigned*)((char*)Bhi + soff(c, q)) = g_f2h[gi];
        *(unsigned*)((char*)Blo + soff(c, q)) = g_f2l[gi];
    }
    __syncthreads();
    layerMMA<128, 128, 4, 2, true>(fr_w3[0], b3, Bhi, Blo, Ahi, Alo, wh, lane, hoff);
    barh(h);
    for (int r = t2; r < 128 * 32; r += 256) {              // pool gather -> A rows 128..255
        int c = r >> 5, q = qb + (r & 31);
        float v0 = g_cf2[((size_t)b * CC + cl0[2 * q]) * 128 + c];
        float v1 = g_cf2[((size_t)b * CC + cl0[2 * q + 1]) * 128 + c];
        unsigned hw, lw; split2(v0, v1, hw, lw);
        *(unsigned*)((char*)Ahi + soff(128 + c, q)) = hw;
        *(unsigned*)((char*)Alo + soff(128 + c, q)) = lw;
    }
    barh(h);
    layerMMA<256, 64, 2, 2, true>(fr_w1[1], b1, Ahi, Alo, Bhi, Blo, wh, lane, hoff);
    barh(h);
    layerMMA<64, 128, 4, 2, true>(fr_w2[1], b2, Bhi, Blo, Ahi, Alo, wh, lane, hoff);
    barh(h);
    for (int r = t2; r < 128 * 32; r += 256) {              // f2' store + segmax cf
        int c = r >> 5, q = qb + (r & 31);
        unsigned h2 = *(unsigned*)((char*)Ahi + soff(c, q));
        unsigned l2 = *(unsigned*)((char*)Alo + soff(c, q));
        size_t gi = ((size_t)(b * 128 + c)) * (NN / 2) + q0 + q;
        g_f2h[gi] = h2; g_f2l[gi] = l2;
        atomicMax(&cfl[cl1[2 * q] * 128 + c], __float_as_int(bflo(h2) + bflo(l2)));
        atomicMax(&cfl[cl1[2 * q + 1] * 128 + c], __float_as_int(bfhi(h2) + bfhi(l2)));
    }
    layerMMA<128, 128, 4, 2, true>(fr_c1[1], bc1, Ahi, Alo, Bhi, Blo, wh, lane, hoff);
    barh(h);
    layerMMA<128, 256, 4, 4, true>(fr_c2[1], bc2, Bhi, Blo, Ahi, Alo, wh, lane, hoff);
    barh(h);
    layerMMA<256, 32, 1, 2, true>(fr_c3[1], bc3, Ahi, Alo, Bhi, Blo, wh, lane, hoff);
    barh(h);
    for (int r = t2; r < 32 * 32; r += 256) {
        int c = r >> 5, q = qb + (r & 31);
        unsigned h2 = *(unsigned*)((char*)Bhi + soff(c, q));
        unsigned l2 = *(unsigned*)((char*)Blo + soff(c, q));
        atomicMax(&ccl[cl1[2 * q] * 32 + c], __float_as_int(bflo(h2) + bflo(l2)));
        atomicMax(&ccl[cl1[2 * q + 1] * 32 + c], __float_as_int(bfhi(h2) + bfhi(l2)));
    }
    __syncthreads();
    for (int r = t; r < CC * 128; r += THREADS) { int v = cfl[r]; if (v) atomicMax(&g_cf[(BB + b) * CC * 128 + r], v); }
    for (int r = t; r < CC * 32; r += THREADS)  { int v = ccl[r]; if (v) atomicMax(&g_cc[(BB + b) * CC * 32 + r], v); }
}

// ---------------- kernel D ----------------
__global__ __launch_bounds__(THREADS, 1) void kD(const int* __restrict__ clus,
                                                 const float* b3, const float* bo1,
                                                 const float* bo2) {
    extern __shared__ char sm[];
    __nv_bfloat16* Ahi = (__nv_bfloat16*)(sm + AHI_OFF);
    __nv_bfloat16* Alo = (__nv_bfloat16*)(sm + ALO_OFF);
    __nv_bfloat16* Bhi = (__nv_bfloat16*)(sm + BHI_OFF);
    __nv_bfloat16* Blo = (__nv_bfloat16*)(sm + BLO_OFF);
    int* cl1 = (int*)(sm + CL_OFF);
    int t = threadIdx.x, w = t >> 5, lane = t & 31;
    int h = w >> 3, wh = w & 7, t2 = t & 255;
    unsigned hoff = (unsigned)h * 128;
    int qb = h * 32;
    int b = blockIdx.x >> 8, nblk = blockIdx.x & 255;
    int n0 = nblk * P, q0 = nblk * (P / 2);

    if (t < P) cl1[t] = clus[(size_t)(BB + b) * NN + n0 + t];
    for (int r = t2; r < 128 * 32; r += 256) {              // load f2' -> B (own half)
        int c = r >> 5, q = qb + (r & 31);
        size_t gi = ((size_t)(b * 128 + c)) * (NN / 2) + q0 + q;
        *(unsigned*)((char*)Bhi + soff(c, q)) = g_f2h[gi];
        *(unsigned*)((char*)Blo + soff(c, q)) = g_f2l[gi];
    }
    __syncthreads();
    layerMMA<128, 128, 4, 2, true>(fr_w3[1], b3, Bhi, Blo, Ahi, Alo, wh, lane, hoff);
    barh(h);
    for (int r = t2; r < 128 * 32; r += 256) {              // pool gather -> A rows 128..255
        int c = r >> 5, q = qb + (r & 31);
        float v0 = g_cf2[((size_t)(BB + b) * CC + cl1[2 * q]) * 128 + c];
        float v1 = g_cf2[((size_t)(BB + b) * CC + cl1[2 * q + 1]) * 128 + c];
        unsigned hw, lw; split2(v0, v1, hw, lw);
        *(unsigned*)((char*)Ahi + soff(128 + c, q)) = hw;
        *(unsigned*)((char*)Alo + soff(128 + c, q)) = lw;
    }
    barh(h);
    layerMMA<256, 128, 4, 2, true>(fr_o1, bo1, Ahi, Alo, Bhi, Blo, wh, lane, hoff);
    barh(h);
    layerMMA<128, 128, 4, 2, true>(fr_o2, bo2, Bhi, Blo, Ahi, Alo, wh, lane, hoff);
    barh(h);
    if (t2 < 128) {
        float m = 0.0f;
        for (int qi = 0; qi < 32; qi++) {
            int q = qb + qi;
            unsigned h2 = *(unsigned*)((char*)Ahi + soff(t2, q));
            unsigned l2 = *(unsigned*)((char*)Alo + soff(t2, q));
            m = fmaxf(m, fmaxf(bflo(h2) + bflo(l2), bfhi(h2) + bfhi(l2)));
        }
        atomicMax(&g_net[b * 128 + t2], __float_as_int(m));
    }
}

// ---------------- kernel E: dense head ----------------
__global__ void kE(const float* __restrict__ dw1, const float* __restrict__ db1,
                   const float* __restrict__ dw2, const float* __restrict__ db2,
                   const float* __restrict__ dw3, const float* __restrict__ db3,
                   float* __restrict__ out) {
    __shared__ float net[BB * 128], l1[BB * 256], l2[BB * 256];
    int t = threadIdx.x;
    for (int r = t; r < BB * 128; r += TE) net[r] = __int_as_float(g_net[r]);
    __syncthreads();
    for (int r = t; r < BB * 256; r += TE) {
        int b = r >> 8, o = r & 255;
        float ss = db1[o];
        for (int i = 0; i < 128; i++) ss = fmaf(net[b * 128 + i], dw1[i * 256 + o], ss);
        l1[r] = ss >= 0.f ? ss : 0.2f * ss;
    }
    __syncthreads();
    for (int r = t; r < BB * 256; r += TE) {
        int b = r >> 8, o = r & 255;
        float ss = db2[o];
        for (int i = 0; i < 256; i++) ss = fmaf(l1[b * 256 + i], dw2[i * 256 + o], ss);
        l2[r] = ss >= 0.f ? ss : 0.2f * ss;
    }
    __syncthreads();
    for (int r = t; r < BB * 40; r += TE) {
        int b = r / 40, o = r % 40;
        float ss = db3[o];
        for (int i = 0; i < 256; i++) ss = fmaf(l2[b * 256 + i], dw3[i * 40 + o], ss);
        out[r] = ss;
    }
}

// ---------------- host launcher ----------------
extern "C" void kernel_launch(void* const* d_in, const int* in_sizes, int n_in,
                              void* d_out, int out_size) {
    const float* feat = (const float*)d_in[0];
    const int*   clus = (const int*)d_in[1];
    const float* w_in = (const float*)d_in[2];
    const float* b_in = (const float*)d_in[3];
    const float* w1   = (const float*)d_in[4];
    const float* b1   = (const float*)d_in[5];
    const float* w2   = (const float*)d_in[6];
    const float* b2   = (const float*)d_in[7];
    const float* w3   = (const float*)d_in[8];
    const float* b3   = (const float*)d_in[9];
    const float* wc1  = (const float*)d_in[10];
    const float* bc1  = (const float*)d_in[11];
    const float* wc2  = (const float*)d_in[12];
    const float* bc2  = (const float*)d_in[13];
    const float* wc3  = (const float*)d_in[14];
    const float* bc3  = (const float*)d_in[15];
    const float* wo1  = (const float*)d_in[16];
    const float* bo1  = (const float*)d_in[17];
    const float* wo2  = (const float*)d_in[18];
    const float* bo2  = (const float*)d_in[19];
    const float* dw1  = (const float*)d_in[20];
    const float* db1  = (const float*)d_in[21];
    const float* dw2  = (const float*)d_in[22];
    const float* db2  = (const float*)d_in[23];
    const float* dw3  = (const float*)d_in[24];
    const float* db3  = (const float*)d_in[25];

    cudaFuncSetAttribute(kA, cudaFuncAttributeMaxDynamicSharedMemorySize, SMEM_BYTES);
    cudaFuncSetAttribute(kC, cudaFuncAttributeMaxDynamicSharedMemorySize, SMEM_BYTES);
    cudaFuncSetAttribute(kD, cudaFuncAttributeMaxDynamicSharedMemorySize, SMEM_BYTES);

    unsigned *p_in, *p_w1, *p_w2, *p_w3, *p_c1, *p_c2, *p_c3, *p_o1, *p_o2;
    cudaGetSymbolAddress((void**)&p_in, fr_in);
    cudaGetSymbolAddress((void**)&p_w1, fr_w1);
    cudaGetSymbolAddress((void**)&p_w2, fr_w2);
    cudaGetSymbolAddress((void**)&p_w3, fr_w3);
    cudaGetSymbolAddress((void**)&p_c1, fr_c1);
    cudaGetSymbolAddress((void**)&p_c2, fr_c2);
    cudaGetSymbolAddress((void**)&p_c3, fr_c3);
    cudaGetSymbolAddress((void**)&p_o1, fr_o1);
    cudaGetSymbolAddress((void**)&p_o2, fr_o2);

    FJobs jobs;
    int idx = 0, total = 0;
    auto add = [&](const float* s, unsigned* d, int Ireal, int Ipad, int O) {
        jobs.src[idx] = s; jobs.dst[idx] = d;
        jobs.Ireal[idx] = Ireal; jobs.Ipad[idx] = Ipad; jobs.O[idx] = O;
        jobs.n[idx] = O * Ipad;
        total += O * Ipad; idx++;
    };
    add(w_in, p_in, KIN, 32, 256);
    for (int it = 0; it < 2; it++) {
        add(w1  + it * 64 * 256,  p_w1 + it * 64 * 256,  256, 256, 64);
        add(w2  + it * 128 * 64,  p_w2 + it * 128 * 64,  64, 64, 128);
        add(w3  + it * 128 * 128, p_w3 + it * 128 * 128, 128, 128, 128);
        add(wc1 + it * 128 * 128, p_c1 + it * 128 * 128, 128, 128, 128);
        add(wc2 + it * 256 * 128, p_c2 + it * 256 * 128, 128, 128, 256);
        add(wc3 + it * 32 * 256,  p_c3 + it * 32 * 256,  256, 256, 32);
    }
    add(wo1, p_o1, 256, 256, 128);
    add(wo2, p_o2, 128, 128, 128);

    // launch order chosen so ncu (-s 5 -c 1) captures kC (6th launch)
    frag_all<<<(total + 255) / 256, 256>>>(jobs, total);  // 1
    zero1_k<<<256, 256>>>();                              // 2
    zero2_k<<<4, 256>>>();                                // 3

    int grid = BB * (NN / P);   // 2048
    kA<<<grid, THREADS, SMEM_BYTES>>>(feat, clus, b_in, b1, b2, bc1, bc2, bc3);   // 4
    kB<<<BB, TE>>>(0);                                                            // 5
    kC<<<grid, THREADS, SMEM_BYTES>>>(clus, b3, b1 + 64, b2 + 128, bc1 + 128, bc2 + 256, bc3 + 32); // 6 <- ncu
    kB<<<BB, TE>>>(1);
    kD<<<grid, THREADS, SMEM_BYTES>>>(clus, b3 + 128, bo1, bo2);
    kE<<<1, TE>>>(dw1, db1, dw2, db2, dw3, db3, (float*)d_out);
}

// round 15
// speedup vs baseline: 1.0020x; 1.0020x over previous
#include <cuda_runtime.h>
#include <cuda_bf16.h>

#define BB 8
#define NN 32768
#define CC 32
#define KIN 22

constexpr int THREADS = 512;  // 16 warps = 2 halves x 8 warps
constexpr int TE = 256;
constexpr int P = 128;        // points per CTA (64 per half)

// ---------------- device scratch ----------------
__device__ unsigned g_f2h[(size_t)BB * 128 * (NN / 2)];
__device__ unsigned g_f2l[(size_t)BB * 128 * (NN / 2)];
__device__ int   g_cf[2 * BB * CC * 128];
__device__ int   g_cc[2 * BB * CC * 32];
__device__ float g_cf2[2 * BB * CC * 128];
__device__ int   g_net[BB * 128];

// weight fragments (u32 = 2 packed bf16): per (mt,ks): 64 uint4 = hi(32)+lo(32)
__device__ unsigned fr_in [256 * 32];
__device__ unsigned fr_w1 [2][64 * 256];
__device__ unsigned fr_w2 [2][128 * 64];
__device__ unsigned fr_w3 [2][128 * 128];
__device__ unsigned fr_c1 [2][128 * 128];
__device__ unsigned fr_c2 [2][256 * 128];
__device__ unsigned fr_c3 [2][32 * 256];
__device__ unsigned fr_o1 [128 * 256];
__device__ unsigned fr_o2 [128 * 128];

// ---------------- prep: pack all weights into MMA fragment layout ------------
struct FJobs {
    const float* src[15];
    unsigned*    dst[15];
    int Ireal[15], Ipad[15], O[15], n[15];
};

__global__ void frag_all(FJobs jobs, int total) {
    int t = blockIdx.x * blockDim.x + threadIdx.x;
    if (t >= total) return;
    int j = 0, e = t;
    while (e >= jobs.n[j]) { e -= jobs.n[j]; j++; }
    int Ireal = jobs.Ireal[j], Ipad = jobs.Ipad[j];
    int KS = Ipad / 16;
    int f = e >> 7;
    int idx = e & 127;
    int lane = idx >> 2, r = idx & 3;
    int term = f & 1, q = f >> 1;
    int ks = q % KS, mt = q / KS;
    int g = lane >> 2, c = lane & 3;
    int row = mt * 16 + g + (r & 1) * 8;
    int k0  = ks * 16 + 2 * c + (r & 2) * 4;
    const float* W = jobs.src[j];
    float v0 = (k0     < Ireal) ? W[row * Ireal + k0]     : 0.0f;
    float v1 = (k0 + 1 < Ireal) ? W[row * Ireal + k0 + 1] : 0.0f;
    unsigned short h0, h1;
    if (term == 0) {
        h0 = __bfloat16_as_ushort(__float2bfloat16(v0));
        h1 = __bfloat16_as_ushort(__float2bfloat16(v1));
    } else {
        __nv_bfloat16 b0 = __float2bfloat16(v0);
        __nv_bfloat16 b1 = __float2bfloat16(v1);
        h0 = __bfloat16_as_ushort(__float2bfloat16(v0 - __bfloat162float(b0)));
        h1 = __bfloat16_as_ushort(__float2bfloat16(v1 - __bfloat162float(b1)));
    }
    jobs.dst[j][e] = (unsigned)h0 | ((unsigned)h1 << 16);
}

__global__ void zero1_k() {
    int t = blockIdx.x * blockDim.x + threadIdx.x;
    if (t < 2 * BB * CC * 128) g_cf[t] = 0;
    if (t < 2 * BB * CC * 32)  g_cc[t] = 0;
}
__global__ void zero2_k() {
    int t = blockIdx.x * blockDim.x + threadIdx.x;
    if (t < BB * 128) g_net[t] = 0;
}

// ---------------- asm helpers ----------------
__device__ __forceinline__ unsigned sptr(const void* p) {
    return (unsigned)__cvta_generic_to_shared(p);
}
__device__ __forceinline__ void barh(int h) {
    asm volatile("bar.sync %0, %1;" :: "r"(h + 1), "r"(256) : "memory");
}
__device__ __forceinline__ void mma16816(float* d, unsigned a0, unsigned a1,
                                         unsigned a2, unsigned a3,
                                         unsigned b0, unsigned b1) {
    asm volatile(
        "mma.sync.aligned.m16n8k16.row.col.f32.bf16.bf16.f32 "
        "{%0,%1,%2,%3}, {%4,%5,%6,%7}, {%8,%9}, {%0,%1,%2,%3};"
        : "+f"(d[0]), "+f"(d[1]), "+f"(d[2]), "+f"(d[3])
        : "r"(a0), "r"(a1), "r"(a2), "r"(a3), "r"(b0), "r"(b1));
}
__device__ __forceinline__ void ldsm_x4_t(unsigned addr, unsigned* r) {
    asm volatile("ldmatrix.sync.aligned.m8n8.x4.trans.shared.b16 {%0,%1,%2,%3}, [%4];"
                 : "=r"(r[0]), "=r"(r[1]), "=r"(r[2]), "=r"(r[3]) : "r"(addr));
}
__device__ __forceinline__ void stsm_x2(unsigned addr, unsigned r0, unsigned r1) {
    asm volatile("stmatrix.sync.aligned.m8n8.x2.shared.b16 [%0], {%1,%2};"
                 :: "r"(addr), "r"(r0), "r"(r1));
}
__device__ __forceinline__ void stsm_x4(unsigned addr, unsigned r0, unsigned r1,
                                        unsigned r2, unsigned r3) {
    asm volatile("stmatrix.sync.aligned.m8n8.x4.shared.b16 [%0], {%1,%2,%3,%4};"
                 :: "r"(addr), "r"(r0), "r"(r1), "r"(r2), "r"(r3));
}
__device__ __forceinline__ unsigned pack_bf(__nv_bfloat16 a, __nv_bfloat16 b) {
    return (unsigned)__bfloat16_as_ushort(a) | ((unsigned)__bfloat16_as_ushort(b) << 16);
}
__device__ __forceinline__ float bflo(unsigned u) {
    return __bfloat162float(__ushort_as_bfloat16((unsigned short)(u & 0xFFFF)));
}
__device__ __forceinline__ float bfhi(unsigned u) {
    return __bfloat162float(__ushort_as_bfloat16((unsigned short)(u >> 16)));
}
__device__ __forceinline__ void split2(float v0, float v1, unsigned& hw, unsigned& lw) {
    __nv_bfloat16 h0 = __float2bfloat16(v0), h1 = __float2bfloat16(v1);
    hw = pack_bf(h0, h1);
    lw = pack_bf(__float2bfloat16(v0 - __bfloat162float(h0)),
                 __float2bfloat16(v1 - __bfloat162float(h1)));
}
// swizzled element offset: row = channel, 256B row, XOR-16B swizzle (within 128B half)
__device__ __forceinline__ int soff(int c, int q) {   // q = point pair index (u32)
    return c * 256 + ((q * 4) ^ ((c & 7) << 4));
}

// ---------------- per-half tensor-core layer: D[O x 64] = W[O x K] * H[K x 64]
// 8 warps per half; warp grid (MT/WM) x (8/WN) == 8; hoff = half byte offset (0/128)
// Weight prefetch (WM<=2); epilogue uses stmatrix.x4 for even WN.
template <int K, int O, int WM, int WN, bool RELU>
__device__ __forceinline__ void layerMMA(const unsigned* __restrict__ WF,
                                         const float* __restrict__ bias,
                                         const __nv_bfloat16* Shi, const __nv_bfloat16* Slo,
                                         __nv_bfloat16* Dhi, __nv_bfloat16* Dlo,
                                         int wh, int lane, unsigned hoff) {
    constexpr int KS = K / 16;
    constexpr int MT = O / 16;
    constexpr int GN = 8 / WN;
    constexpr bool PF = (WM <= 2);
    static_assert((MT / WM) * GN == 8, "warp grid");
    static_assert(WN >= 2, "x4 path only");
    int gm = wh / GN, gn = wh % GN;
    int g = lane >> 2;
    float acc[WM][WN][4];
#pragma unroll
    for (int i = 0; i < WM; i++) {
        int mr = (gm * WM + i) * 16 + g;
        float b0 = __ldg(bias + mr), b1 = __ldg(bias + mr + 8);
#pragma unroll
        for (int j = 0; j < WN; j++) {
            acc[i][j][0] = b0; acc[i][j][1] = b0;
            acc[i][j][2] = b1; acc[i][j][3] = b1;
        }
    }
    int krow = ((lane >> 3) & 1) * 8 + (lane & 7);
    unsigned swz = ((unsigned)(krow & 7)) << 4;
    int ntoff = lane >> 4;
    unsigned baseH = sptr(Shi) + krow * 256 + hoff;
    unsigned baseL = sptr(Slo) + krow * 256 + hoff;

    uint4 ahc[WM], alc[WM];
    if (PF) {
#pragma unroll
        for (int i = 0; i < WM; i++) {
            const uint4* bp = reinterpret_cast<const uint4*>(WF) + ((gm * WM + i) * KS) * 64 + lane;
            ahc[i] = __ldg(bp); alc[i] = __ldg(bp + 32);
        }
    }
#pragma unroll
    for (int ks = 0; ks < KS; ks++) {
        uint4 ahn[WM], aln[WM];
        if (PF) {
            if (ks + 1 < KS) {
#pragma unroll
                for (int i = 0; i < WM; i++) {
                    const uint4* bp = reinterpret_cast<const uint4*>(WF) + ((gm * WM + i) * KS + ks + 1) * 64 + lane;
                    ahn[i] = __ldg(bp); aln[i] = __ldg(bp + 32);
                }
            }
        } else {
#pragma unroll
            for (int i = 0; i < WM; i++) {
                const uint4* bp = reinterpret_cast<const uint4*>(WF) + ((gm * WM + i) * KS + ks) * 64 + lane;
                ahc[i] = __ldg(bp); alc[i] = __ldg(bp + 32);
            }
        }
        unsigned koff = (unsigned)ks * 4096;
        constexpr int NP = WN / 2;
        unsigned bh[NP][4], bl[NP][4];
#pragma unroll
        for (int jp = 0; jp < NP; jp++) {
            unsigned col = ((unsigned)((gn * WN + 2 * jp + ntoff) * 16)) ^ swz;
            ldsm_x4_t(baseH + koff + col, bh[jp]);
            ldsm_x4_t(baseL + koff + col, bl[jp]);
        }
#pragma unroll
        for (int jp = 0; jp < NP; jp++)
#pragma unroll
            for (int i = 0; i < WM; i++) {
                mma16816(acc[i][2 * jp],     ahc[i].x, ahc[i].y, ahc[i].z, ahc[i].w, bh[jp][0], bh[jp][1]);
                mma16816(acc[i][2 * jp],     ahc[i].x, ahc[i].y, ahc[i].z, ahc[i].w, bl[jp][0], bl[jp][1]);
                mma16816(acc[i][2 * jp],     alc[i].x, alc[i].y, alc[i].z, alc[i].w, bh[jp][0], bh[jp][1]);
                mma16816(acc[i][2 * jp + 1], ahc[i].x, ahc[i].y, ahc[i].z, ahc[i].w, bh[jp][2], bh[jp][3]);
                mma16816(acc[i][2 * jp + 1], ahc[i].x, ahc[i].y, ahc[i].z, ahc[i].w, bl[jp][2], bl[jp][3]);
                mma16816(acc[i][2 * jp + 1], alc[i].x, alc[i].y, alc[i].z, alc[i].w, bh[jp][2], bh[jp][3]);
            }
        if (PF && ks + 1 < KS) {
#pragma unroll
            for (int i = 0; i < WM; i++) { ahc[i] = ahn[i]; alc[i] = aln[i]; }
        }
    }
    // epilogue: stmatrix.x4 — 4 tiles (2 n-cols x 2 row-halves) per instruction
    int tl = lane >> 3;                  // 0..3 -> tile index
#pragma unroll
    for (int i = 0; i < WM; i++) {
        int mrow = (gm * WM + i) * 16 + (tl & 1) * 8 + (lane & 7);
        unsigned sswz = ((unsigned)(mrow & 7)) << 4;
        unsigned bH = sptr(Dhi) + mrow * 256 + hoff;
        unsigned bL = sptr(Dlo) + mrow * 256 + hoff;
#pragma unroll
        for (int jp = 0; jp < WN / 2; jp++) {
            int jme = gn * WN + 2 * jp + (tl >> 1);          // this lane's column
            unsigned addrcol = ((unsigned)(jme * 16)) ^ sswz;
            // packed data for BOTH columns of the pair
            unsigned h0[2], h1[2], l0[2], l1[2];
#pragma unroll
            for (int jj = 0; jj < 2; jj++) {
                int j = 2 * jp + jj;
                float d0 = acc[i][j][0], d1 = acc[i][j][1], d2 = acc[i][j][2], d3 = acc[i][j][3];
                if (RELU) {
                    d0 = fmaxf(d0, 0.f); d1 = fmaxf(d1, 0.f);
                    d2 = fmaxf(d2, 0.f); d3 = fmaxf(d3, 0.f);
                }
                split2(d0, d1, h0[jj], l0[jj]);
                split2(d2, d3, h1[jj], l1[jj]);
            }
            stsm_x4(bH + addrcol, h0[0], h1[0], h0[1], h1[1]);
            stsm_x4(bL + addrcol, l0[0], l1[0], l0[1], l1[1]);
        }
    }
}

// shared layout (bytes): A 256ch, B 128ch, rows = 256B swizzled
constexpr int AHI_OFF = 0;
constexpr int ALO_OFF = 65536;
constexpr int BHI_OFF = 131072;
constexpr int BLO_OFF = 163840;
constexpr int CFL_OFF = 196608;
constexpr int CCL_OFF = 212992;
constexpr int CL_OFF  = 217088;
constexpr int SMEM_BYTES = 218112;

// ---------------- kernel A ----------------
__global__ __launch_bounds__(THREADS, 1) void kA(const float* __restrict__ feat,
                                                 const int* __restrict__ clus,
                                                 const float* b_in, const float* b1,
                                                 const float* b2, const float* bc1,
                                                 const float* bc2, const float* bc3) {
    extern __shared__ char sm[];
    __nv_bfloat16* Ahi = (__nv_bfloat16*)(sm + AHI_OFF);
    __nv_bfloat16* Alo = (__nv_bfloat16*)(sm + ALO_OFF);
    __nv_bfloat16* Bhi = (__nv_bfloat16*)(sm + BHI_OFF);
    __nv_bfloat16* Blo = (__nv_bfloat16*)(sm + BLO_OFF);
    int* cfl = (int*)(sm + CFL_OFF);
    int* ccl = (int*)(sm + CCL_OFF);
    int* cl  = (int*)(sm + CL_OFF);
    int t = threadIdx.x, w = t >> 5, lane = t & 31;
    int h = w >> 3, wh = w & 7, t2 = t & 255;
    unsigned hoff = (unsigned)h * 128;
    int qb = h * 32;
    int b = blockIdx.x >> 8, nblk = blockIdx.x & 255;
    int n0 = nblk * P, q0 = nblk * (P / 2);

    for (int r = t; r < CC * 128; r += THREADS) cfl[r] = 0;
    for (int r = t; r < CC * 32; r += THREADS)  ccl[r] = 0;
    if (t < P) cl[t] = clus[(size_t)b * NN + n0 + t];
    for (int r = t2; r < 32 * 32; r += 256) {               // features pad 22->32 (own half)
        int c = r >> 5, q = qb + (r & 31);
        float v0 = (c < KIN) ? feat[((size_t)b * NN + n0 + 2 * q) * KIN + c] : 0.0f;
        float v1 = (c < KIN) ? feat[((size_t)b * NN + n0 + 2 * q + 1) * KIN + c] : 0.0f;
        unsigned hw, lw; split2(v0, v1, hw, lw);
        *(unsigned*)((char*)Bhi + soff(c, q)) = hw;
        *(unsigned*)((char*)Blo + soff(c, q)) = lw;
    }
    __syncthreads();
    layerMMA<32, 256, 4, 4, true>(fr_in, b_in, Bhi, Blo, Ahi, Alo, wh, lane, hoff);
    barh(h);
    layerMMA<256, 64, 2, 2, true>(fr_w1[0], b1, Ahi, Alo, Bhi, Blo, wh, lane, hoff);
    barh(h);
    layerMMA<64, 128, 2, 4, true>(fr_w2[0], b2, Bhi, Blo, Ahi, Alo, wh, lane, hoff);
    barh(h);
    for (int r = t2; r < 128 * 32; r += 256) {              // f2 store + segmax cf (own half)
        int c = r >> 5, q = qb + (r & 31);
        unsigned h2 = *(unsigned*)((char*)Ahi + soff(c, q));
        unsigned l2 = *(unsigned*)((char*)Alo + soff(c, q));
        size_t gi = ((size_t)(b * 128 + c)) * (NN / 2) + q0 + q;
        g_f2h[gi] = h2; g_f2l[gi] = l2;
        atomicMax(&cfl[cl[2 * q] * 128 + c], __float_as_int(bflo(h2) + bflo(l2)));
        atomicMax(&cfl[cl[2 * q + 1] * 128 + c], __float_as_int(bfhi(h2) + bfhi(l2)));
    }
    layerMMA<128, 128, 2, 4, true>(fr_c1[0], bc1, Ahi, Alo, Bhi, Blo, wh, lane, hoff);
    barh(h);
    layerMMA<128, 256, 4, 4, true>(fr_c2[0], bc2, Bhi, Blo, Ahi, Alo, wh, lane, hoff);
    barh(h);
    layerMMA<256, 32, 1, 2, true>(fr_c3[0], bc3, Ahi, Alo, Bhi, Blo, wh, lane, hoff);
    barh(h);
    for (int r = t2; r < 32 * 32; r += 256) {               // segmax cc (own half)
        int c = r >> 5, q = qb + (r & 31);
        unsigned h2 = *(unsigned*)((char*)Bhi + soff(c, q));
        unsigned l2 = *(unsigned*)((char*)Blo + soff(c, q));
        atomicMax(&ccl[cl[2 * q] * 32 + c], __float_as_int(bflo(h2) + bflo(l2)));
        atomicMax(&ccl[cl[2 * q + 1] * 32 + c], __float_as_int(bfhi(h2) + bfhi(l2)));
    }
    __syncthreads();
    for (int r = t; r < CC * 128; r += THREADS) { int v = cfl[r]; if (v) atomicMax(&g_cf[b * CC * 128 + r], v); }
    for (int r = t; r < CC * 32; r += THREADS)  { int v = ccl[r]; if (v) atomicMax(&g_cc[b * CC * 32 + r], v); }
}

// ---------------- kernel B: per-batch corr matrix + cf @ corr ----------------
__global__ void kB(int it) {
    __shared__ float cm[CC * 32], corr[CC * CC], invn[CC], cfs[CC * 128];
    int b = blockIdx.x, t = threadIdx.x;
    for (int r = t; r < CC * 32; r += TE)  cm[r]  = __int_as_float(g_cc[(it * BB + b) * CC * 32 + r]);
    for (int r = t; r < CC * 128; r += TE) cfs[r] = __int_as_float(g_cf[(it * BB + b) * CC * 128 + r]);
    __syncthreads();
    if (t < CC) {
        float ss = 0.f;
        for (int c = 0; c < 32; c++) { float v = cm[t * 32 + c]; ss += v * v; }
        invn[t] = 1.0f / fmaxf(sqrtf(ss), 1e-12f);
    }
    __syncthreads();
    for (int r = t; r < CC * 32; r += TE) cm[r] *= invn[r >> 5];
    __syncthreads();
    for (int r = t; r < CC * CC; r += TE) {
        int c1 = r >> 5, c2 = r & 31;
        float ss = 0.f;
        for (int c = 0; c < 32; c++) ss += cm[c1 * 32 + c] * cm[c2 * 32 + c];
        corr[r] = ss;
    }
    __syncthreads();
    for (int r = t; r < CC * 128; r += TE) {
        int c2 = r >> 7, ch = r & 127;
        float ss = 0.f;
        for (int c1 = 0; c1 < 32; c1++) ss += cfs[c1 * 128 + ch] * corr[c1 * 32 + c2];
        g_cf2[(it * BB + b) * CC * 128 + r] = ss;
    }
}

// ---------------- kernel C ----------------
__global__ __launch_bounds__(THREADS, 1) void kC(const int* __restrict__ clus,
                                                 const float* b3, const float* b1,
                                                 const float* b2, const float* bc1,
                                                 const float* bc2, const float* bc3) {
    extern __shared__ char sm[];
    __nv_bfloat16* Ahi = (__nv_bfloat16*)(sm + AHI_OFF);
    __nv_bfloat16* Alo = (__nv_bfloat16*)(sm + ALO_OFF);
    __nv_bfloat16* Bhi = (__nv_bfloat16*)(sm + BHI_OFF);
    __nv_bfloat16* Blo = (__nv_bfloat16*)(sm + BLO_OFF);
    int* cfl = (int*)(sm + CFL_OFF);
    int* ccl = (int*)(sm + CCL_OFF);
    int* cl0 = (int*)(sm + CL_OFF);
    int* cl1 = cl0 + 128;
    int t = threadIdx.x, w = t >> 5, lane = t & 31;
    int h = w >> 3, wh = w & 7, t2 = t & 255;
    unsigned hoff = (unsigned)h * 128;
    int qb = h * 32;
    int b = blockIdx.x >> 8, nblk = blockIdx.x & 255;
    int n0 = nblk * P, q0 = nblk * (P / 2);

    for (int r = t; r < CC * 128; r += THREADS) cfl[r] = 0;
    for (int r = t; r < CC * 32; r += THREADS)  ccl[r] = 0;
    if (t < P) {
        cl0[t] = clus[(size_t)b * NN + n0 + t];
        cl1[t] = clus[(size_t)(BB + b) * NN + n0 + t];
    }
    for (int r = t2; r < 128 * 32; r += 256) {              // load f2 -> B (own half)
        int c = r >> 5, q = qb + (r & 31);
        size_t gi = ((size_t)(b * 128 + c)) * (NN / 2) + q0 + q;
        *(unsigned*)((char*)Bhi + soff(c, q)) = g_f2h[gi];
        *(unsigned*)((char*)Blo + soff(c, q)) = g_f2l[gi];
    }
    __syncthreads();
    layerMMA<128, 128, 2, 4, true>(fr_w3[0], b3, Bhi, Blo, Ahi, Alo, wh, lane, hoff);
    barh(h);
    for (int r = t2; r < 128 * 32; r += 256) {              // pool gather -> A rows 128..255
        int c = r >> 5, q = qb + (r & 31);
        float v0 = g_cf2[((size_t)b * CC + cl0[2 * q]) * 128 + c];
        float v1 = g_cf2[((size_t)b * CC + cl0[2 * q + 1]) * 128 + c];
        unsigned hw, lw; split2(v0, v1, hw, lw);
        *(unsigned*)((char*)Ahi + soff(128 + c, q)) = hw;
        *(unsigned*)((char*)Alo + soff(128 + c, q)) = lw;
    }
    barh(h);
    layerMMA<256, 64, 2, 2, true>(fr_w1[1], b1, Ahi, Alo, Bhi, Blo, wh, lane, hoff);
    barh(h);
    layerMMA<64, 128, 2, 4, true>(fr_w2[1], b2, Bhi, Blo, Ahi, Alo, wh, lane, hoff);
    barh(h);
    for (int r = t2; r < 128 * 32; r += 256) {              // f2' store + segmax cf
        int c = r >> 5, q = qb + (r & 31);
        unsigned h2 = *(unsigned*)((char*)Ahi + soff(c, q));
        unsigned l2 = *(unsigned*)((char*)Alo + soff(c, q));
        size_t gi = ((size_t)(b * 128 + c)) * (NN / 2) + q0 + q;
        g_f2h[gi] = h2; g_f2l[gi] = l2;
        atomicMax(&cfl[cl1[2 * q] * 128 + c], __float_as_int(bflo(h2) + bflo(l2)));
        atomicMax(&cfl[cl1[2 * q + 1] * 128 + c], __float_as_int(bfhi(h2) + bfhi(l2)));
    }
    layerMMA<128, 128, 2, 4, true>(fr_c1[1], bc1, Ahi, Alo, Bhi, Blo, wh, lane, hoff);
    barh(h);
    layerMMA<128, 256, 4, 4, true>(fr_c2[1], bc2, Bhi, Blo, Ahi, Alo, wh, lane, hoff);
    barh(h);
    layerMMA<256, 32, 1, 2, true>(fr_c3[1], bc3, Ahi, Alo, Bhi, Blo, wh, lane, hoff);
    barh(h);
    for (int r = t2; r < 32 * 32; r += 256) {
        int c = r >> 5, q = qb + (r & 31);
        unsigned h2 = *(unsigned*)((char*)Bhi + soff(c, q));
        unsigned l2 = *(unsigned*)((char*)Blo + soff(c, q));
        atomicMax(&ccl[cl1[2 * q] * 32 + c], __float_as_int(bflo(h2) + bflo(l2)));
        atomicMax(&ccl[cl1[2 * q + 1] * 32 + c], __float_as_int(bfhi(h2) + bfhi(l2)));
    }
    __syncthreads();
    for (int r = t; r < CC * 128; r += THREADS) { int v = cfl[r]; if (v) atomicMax(&g_cf[(BB + b) * CC * 128 + r], v); }
    for (int r = t; r < CC * 32; r += THREADS)  { int v = ccl[r]; if (v) atomicMax(&g_cc[(BB + b) * CC * 32 + r], v); }
}

// ---------------- kernel D ----------------
__global__ __launch_bounds__(THREADS, 1) void kD(const int* __restrict__ clus,
                                                 const float* b3, const float* bo1,
                                                 const float* bo2) {
    extern __shared__ char sm[];
    __nv_bfloat16* Ahi = (__nv_bfloat16*)(sm + AHI_OFF);
    __nv_bfloat16* Alo = (__nv_bfloat16*)(sm + ALO_OFF);
    __nv_bfloat16* Bhi = (__nv_bfloat16*)(sm + BHI_OFF);
    __nv_bfloat16* Blo = (__nv_bfloat16*)(sm + BLO_OFF);
    int* cl1 = (int*)(sm + CL_OFF);
    int t = threadIdx.x, w = t >> 5, lane = t & 31;
    int h = w >> 3, wh = w & 7, t2 = t & 255;
    unsigned hoff = (unsigned)h * 128;
    int qb = h * 32;
    int b = blockIdx.x >> 8, nblk = blockIdx.x & 255;
    int n0 = nblk * P, q0 = nblk * (P / 2);

    if (t < P) cl1[t] = clus[(size_t)(BB + b) * NN + n0 + t];
    for (int r = t2; r < 128 * 32; r += 256) {              // load f2' -> B (own half)
        int c = r >> 5, q = qb + (r & 31);
        size_t gi = ((size_t)(b * 128 + c)) * (NN / 2) + q0 + q;
        *(unsigned*)((char*)Bhi + soff(c, q)) = g_f2h[gi];
        *(unsigned*)((char*)Blo + soff(c, q)) = g_f2l[gi];
    }
    __syncthreads();
    layerMMA<128, 128, 2, 4, true>(fr_w3[1], b3, Bhi, Blo, Ahi, Alo, wh, lane, hoff);
    barh(h);
    for (int r = t2; r < 128 * 32; r += 256) {              // pool gather -> A rows 128..255
        int c = r >> 5, q = qb + (r & 31);
        float v0 = g_cf2[((size_t)(BB + b) * CC + cl1[2 * q]) * 128 + c];
        float v1 = g_cf2[((size_t)(BB + b) * CC + cl1[2 * q + 1]) * 128 + c];
        unsigned hw, lw; split2(v0, v1, hw, lw);
        *(unsigned*)((char*)Ahi + soff(128 + c, q)) = hw;
        *(unsigned*)((char*)Alo + soff(128 + c, q)) = lw;
    }
    barh(h);
    layerMMA<256, 128, 2, 4, true>(fr_o1, bo1, Ahi, Alo, Bhi, Blo, wh, lane, hoff);
    barh(h);
    layerMMA<128, 128, 2, 4, true>(fr_o2, bo2, Bhi, Blo, Ahi, Alo, wh, lane, hoff);
    barh(h);
    if (t2 < 128) {
        float m = 0.0f;
        for (int qi = 0; qi < 32; qi++) {
            int q = qb + qi;
            unsigned h2 = *(unsigned*)((char*)Ahi + soff(t2, q));
            unsigned l2 = *(unsigned*)((char*)Alo + soff(t2, q));
            m = fmaxf(m, fmaxf(bflo(h2) + bflo(l2), bfhi(h2) + bfhi(l2)));
        }
        atomicMax(&g_net[b * 128 + t2], __float_as_int(m));
    }
}

// ---------------- kernel E: dense head ----------------
__global__ void kE(const float* __restrict__ dw1, const float* __restrict__ db1,
                   const float* __restrict__ dw2, const float* __restrict__ db2,
                   const float* __restrict__ dw3, const float* __restrict__ db3,
                   float* __restrict__ out) {
    __shared__ float net[BB * 128], l1[BB * 256], l2[BB * 256];
    int t = threadIdx.x;
    for (int r = t; r < BB * 128; r += TE) net[r] = __int_as_float(g_net[r]);
    __syncthreads();
    for (int r = t; r < BB * 256; r += TE) {
        int b = r >> 8, o = r & 255;
        float ss = db1[o];
        for (int i = 0; i < 128; i++) ss = fmaf(net[b * 128 + i], dw1[i * 256 + o], ss);
        l1[r] = ss >= 0.f ? ss : 0.2f * ss;
    }
    __syncthreads();
    for (int r = t; r < BB * 256; r += TE) {
        int b = r >> 8, o = r & 255;
        float ss = db2[o];
        for (int i = 0; i < 256; i++) ss = fmaf(l1[b * 256 + i], dw2[i * 256 + o], ss);
        l2[r] = ss >= 0.f ? ss : 0.2f * ss;
    }
    __syncthreads();
    for (int r = t; r < BB * 40; r += TE) {
        int b = r / 40, o = r % 40;
        float ss = db3[o];
        for (int i = 0; i < 256; i++) ss = fmaf(l2[b * 256 + i], dw3[i * 40 + o], ss);
        out[r] = ss;
    }
}

// ---------------- host launcher ----------------
extern "C" void kernel_launch(void* const* d_in, const int* in_sizes, int n_in,
                              void* d_out, int out_size) {
    const float* feat = (const float*)d_in[0];
    const int*   clus = (const int*)d_in[1];
    const float* w_in = (const float*)d_in[2];
    const float* b_in = (const float*)d_in[3];
    const float* w1   = (const float*)d_in[4];
    const float* b1   = (const float*)d_in[5];
    const float* w2   = (const float*)d_in[6];
    const float* b2   = (const float*)d_in[7];
    const float* w3   = (const float*)d_in[8];
    const float* b3   = (const float*)d_in[9];
    const float* wc1  = (const float*)d_in[10];
    const float* bc1  = (const float*)d_in[11];
    const float* wc2  = (const float*)d_in[12];
    const float* bc2  = (const float*)d_in[13];
    const float* wc3  = (const float*)d_in[14];
    const float* bc3  = (const float*)d_in[15];
    const float* wo1  = (const float*)d_in[16];
    const float* bo1  = (const float*)d_in[17];
    const float* wo2  = (const float*)d_in[18];
    const float* bo2  = (const float*)d_in[19];
    const float* dw1  = (const float*)d_in[20];
    const float* db1  = (const float*)d_in[21];
    const float* dw2  = (const float*)d_in[22];
    const float* db2  = (const float*)d_in[23];
    const float* dw3  = (const float*)d_in[24];
    const float* db3  = (const float*)d_in[25];

    cudaFuncSetAttribute(kA, cudaFuncAttributeMaxDynamicSharedMemorySize, SMEM_BYTES);
    cudaFuncSetAttribute(kC, cudaFuncAttributeMaxDynamicSharedMemorySize, SMEM_BYTES);
    cudaFuncSetAttribute(kD, cudaFuncAttributeMaxDynamicSharedMemorySize, SMEM_BYTES);

    unsigned *p_in, *p_w1, *p_w2, *p_w3, *p_c1, *p_c2, *p_c3, *p_o1, *p_o2;
    cudaGetSymbolAddress((void**)&p_in, fr_in);
    cudaGetSymbolAddress((void**)&p_w1, fr_w1);
    cudaGetSymbolAddress((void**)&p_w2, fr_w2);
    cudaGetSymbolAddress((void**)&p_w3, fr_w3);
    cudaGetSymbolAddress((void**)&p_c1, fr_c1);
    cudaGetSymbolAddress((void**)&p_c2, fr_c2);
    cudaGetSymbolAddress((void**)&p_c3, fr_c3);
    cudaGetSymbolAddress((void**)&p_o1, fr_o1);
    cudaGetSymbolAddress((void**)&p_o2, fr_o2);

    FJobs jobs;
    int idx = 0, total = 0;
    auto add = [&](const float* s, unsigned* d, int Ireal, int Ipad, int O) {
        jobs.src[idx] = s; jobs.dst[idx] = d;
        jobs.Ireal[idx] = Ireal; jobs.Ipad[idx] = Ipad; jobs.O[idx] = O;
        jobs.n[idx] = O * Ipad;
        total += O * Ipad; idx++;
    };
    add(w_in, p_in, KIN, 32, 256);
    for (int it = 0; it < 2; it++) {
        add(w1  + it * 64 * 256,  p_w1 + it * 64 * 256,  256, 256, 64);
        add(w2  + it * 128 * 64,  p_w2 + it * 128 * 64,  64, 64, 128);
        add(w3  + it * 128 * 128, p_w3 + it * 128 * 128, 128, 128, 128);
        add(wc1 + it * 128 * 128, p_c1 + it * 128 * 128, 128, 128, 128);
        add(wc2 + it * 256 * 128, p_c2 + it * 256 * 128, 128, 128, 256);
        add(wc3 + it * 32 * 256,  p_c3 + it * 32 * 256,  256, 256, 32);
    }
    add(wo1, p_o1, 256, 256, 128);
    add(wo2, p_o2, 128, 128, 128);

    // launch order chosen so ncu (-s 5 -c 1) captures kC (6th launch)
    frag_all<<<(total + 255) / 256, 256>>>(jobs, total);  // 1
    zero1_k<<<256, 256>>>();                              // 2
    zero2_k<<<4, 256>>>();                                // 3

    int grid = BB * (NN / P);   // 2048
    kA<<<grid, THREADS, SMEM_BYTES>>>(feat, clus, b_in, b1, b2, bc1, bc2, bc3);   // 4
    kB<<<BB, TE>>>(0);                                                            // 5
    kC<<<grid, THREADS, SMEM_BYTES>>>(clus, b3, b1 + 64, b2 + 128, bc1 + 128, bc2 + 256, bc3 + 32); // 6 <- ncu
    kB<<<BB, TE>>>(1);
    kD<<<grid, THREADS, SMEM_BYTES>>>(clus, b3 + 128, bo1, bo2);
    kE<<<1, TE>>>(dw1, db1, dw2, db2, dw3, db3, (float*)d_out);
}

// round 16
// speedup vs baseline: 1.1380x; 1.1358x over previous
#include <cuda_runtime.h>
#include <cuda_bf16.h>

#define BB 8
#define NN 32768
#define CC 32
#define KIN 22

constexpr int THREADS = 256;  // 8 warps, 2 CTAs/SM
constexpr int TE = 256;
constexpr int P = 64;         // points per CTA

// ---------------- device scratch ----------------
__device__ unsigned g_f2h[(size_t)BB * 128 * (NN / 2)];
__device__ unsigned g_f2l[(size_t)BB * 128 * (NN / 2)];
__device__ int   g_cf[2 * BB * CC * 128];
__device__ int   g_cc[2 * BB * CC * 32];
__device__ float g_cf2[2 * BB * CC * 128];
__device__ int   g_net[BB * 128];

// weight fragments (u32 = 2 packed bf16): per (mt,ks): 64 uint4 = hi(32)+lo(32)
__device__ unsigned fr_in [256 * 32];
__device__ unsigned fr_w1 [2][64 * 256];
__device__ unsigned fr_w2 [2][128 * 64];
__device__ unsigned fr_w3 [2][128 * 128];
__device__ unsigned fr_c1 [2][128 * 128];
__device__ unsigned fr_c2 [2][256 * 128];
__device__ unsigned fr_c3 [2][32 * 256];
__device__ unsigned fr_o1 [128 * 256];
__device__ unsigned fr_o2 [128 * 128];

// ---------------- prep: pack all weights into MMA fragment layout ------------
struct FJobs {
    const float* src[15];
    unsigned*    dst[15];
    int Ireal[15], Ipad[15], O[15], n[15];
};

__global__ void frag_all(FJobs jobs, int total) {
    int t = blockIdx.x * blockDim.x + threadIdx.x;
    if (t >= total) return;
    int j = 0, e = t;
    while (e >= jobs.n[j]) { e -= jobs.n[j]; j++; }
    int Ireal = jobs.Ireal[j], Ipad = jobs.Ipad[j];
    int KS = Ipad / 16;
    int f = e >> 7;
    int idx = e & 127;
    int lane = idx >> 2, r = idx & 3;
    int term = f & 1, q = f >> 1;
    int ks = q % KS, mt = q / KS;
    int g = lane >> 2, c = lane & 3;
    int row = mt * 16 + g + (r & 1) * 8;
    int k0  = ks * 16 + 2 * c + (r & 2) * 4;
    const float* W = jobs.src[j];
    float v0 = (k0     < Ireal) ? W[row * Ireal + k0]     : 0.0f;
    float v1 = (k0 + 1 < Ireal) ? W[row * Ireal + k0 + 1] : 0.0f;
    unsigned short h0, h1;
    if (term == 0) {
        h0 = __bfloat16_as_ushort(__float2bfloat16(v0));
        h1 = __bfloat16_as_ushort(__float2bfloat16(v1));
    } else {
        __nv_bfloat16 b0 = __float2bfloat16(v0);
        __nv_bfloat16 b1 = __float2bfloat16(v1);
        h0 = __bfloat16_as_ushort(__float2bfloat16(v0 - __bfloat162float(b0)));
        h1 = __bfloat16_as_ushort(__float2bfloat16(v1 - __bfloat162float(b1)));
    }
    jobs.dst[j][e] = (unsigned)h0 | ((unsigned)h1 << 16);
}

__global__ void zero1_k() {
    int t = blockIdx.x * blockDim.x + threadIdx.x;
    if (t < 2 * BB * CC * 128) g_cf[t] = 0;
    if (t < 2 * BB * CC * 32)  g_cc[t] = 0;
}
__global__ void zero2_k() {
    int t = blockIdx.x * blockDim.x + threadIdx.x;
    if (t < BB * 128) g_net[t] = 0;
}

// ---------------- asm helpers ----------------
__device__ __forceinline__ unsigned sptr(const void* p) {
    return (unsigned)__cvta_generic_to_shared(p);
}
__device__ __forceinline__ void mma16816(float* d, unsigned a0, unsigned a1,
                                         unsigned a2, unsigned a3,
                                         unsigned b0, unsigned b1) {
    asm volatile(
        "mma.sync.aligned.m16n8k16.row.col.f32.bf16.bf16.f32 "
        "{%0,%1,%2,%3}, {%4,%5,%6,%7}, {%8,%9}, {%0,%1,%2,%3};"
        : "+f"(d[0]), "+f"(d[1]), "+f"(d[2]), "+f"(d[3])
        : "r"(a0), "r"(a1), "r"(a2), "r"(a3), "r"(b0), "r"(b1));
}
__device__ __forceinline__ void ldsm_x4_t(unsigned addr, unsigned* r) {
    asm volatile("ldmatrix.sync.aligned.m8n8.x4.trans.shared.b16 {%0,%1,%2,%3}, [%4];"
                 : "=r"(r[0]), "=r"(r[1]), "=r"(r[2]), "=r"(r[3]) : "r"(addr));
}
__device__ __forceinline__ void stsm_x2(unsigned addr, unsigned r0, unsigned r1) {
    asm volatile("stmatrix.sync.aligned.m8n8.x2.shared.b16 [%0], {%1,%2};"
                 :: "r"(addr), "r"(r0), "r"(r1));
}
__device__ __forceinline__ unsigned pack_bf(__nv_bfloat16 a, __nv_bfloat16 b) {
    return (unsigned)__bfloat16_as_ushort(a) | ((unsigned)__bfloat16_as_ushort(b) << 16);
}
__device__ __forceinline__ float bflo(unsigned u) {
    return __bfloat162float(__ushort_as_bfloat16((unsigned short)(u & 0xFFFF)));
}
__device__ __forceinline__ float bfhi(unsigned u) {
    return __bfloat162float(__ushort_as_bfloat16((unsigned short)(u >> 16)));
}
__device__ __forceinline__ void split2(float v0, float v1, unsigned& hw, unsigned& lw) {
    __nv_bfloat16 h0 = __float2bfloat16(v0), h1 = __float2bfloat16(v1);
    hw = pack_bf(h0, h1);
    lw = pack_bf(__float2bfloat16(v0 - __bfloat162float(h0)),
                 __float2bfloat16(v1 - __bfloat162float(h1)));
}
// swizzled element offset: row = channel, 128B row, XOR-16B swizzle
__device__ __forceinline__ int soff(int c, int q) {   // q = point pair index (u32), 0..31
    return c * 128 + ((q * 4) ^ ((c & 7) << 4));
}

// ---------------- tensor-core layer: D[O x 64] = W[O x K] * H[K x 64]
// 8 warps; warp grid (MT/WM) x (8/WN) == 8
template <int K, int O, int WM, int WN, bool RELU>
__device__ __forceinline__ void layerMMA(const unsigned* __restrict__ WF,
                                         const float* __restrict__ bias,
                                         const __nv_bfloat16* Shi, const __nv_bfloat16* Slo,
                                         __nv_bfloat16* Dhi, __nv_bfloat16* Dlo,
                                         int wh, int lane) {
    constexpr int KS = K / 16;
    constexpr int MT = O / 16;
    constexpr int GN = 8 / WN;
    constexpr bool PF = (WM <= 2);
    static_assert((MT / WM) * GN == 8, "warp grid");
    static_assert(WN >= 2, "x4 path only");
    int gm = wh / GN, gn = wh % GN;
    int g = lane >> 2;
    float acc[WM][WN][4];
#pragma unroll
    for (int i = 0; i < WM; i++) {
        int mr = (gm * WM + i) * 16 + g;
        float b0 = __ldg(bias + mr), b1 = __ldg(bias + mr + 8);
#pragma unroll
        for (int j = 0; j < WN; j++) {
            acc[i][j][0] = b0; acc[i][j][1] = b0;
            acc[i][j][2] = b1; acc[i][j][3] = b1;
        }
    }
    int krow = ((lane >> 3) & 1) * 8 + (lane & 7);
    unsigned swz = ((unsigned)(krow & 7)) << 4;
    int ntoff = lane >> 4;
    unsigned baseH = sptr(Shi) + krow * 128;
    unsigned baseL = sptr(Slo) + krow * 128;

    uint4 ahc[WM], alc[WM];
    if (PF) {
#pragma unroll
        for (int i = 0; i < WM; i++) {
            const uint4* bp = reinterpret_cast<const uint4*>(WF) + ((gm * WM + i) * KS) * 64 + lane;
            ahc[i] = __ldg(bp); alc[i] = __ldg(bp + 32);
        }
    }
#pragma unroll
    for (int ks = 0; ks < KS; ks++) {
        uint4 ahn[WM], aln[WM];
        if (PF) {
            if (ks + 1 < KS) {
#pragma unroll
                for (int i = 0; i < WM; i++) {
                    const uint4* bp = reinterpret_cast<const uint4*>(WF) + ((gm * WM + i) * KS + ks + 1) * 64 + lane;
                    ahn[i] = __ldg(bp); aln[i] = __ldg(bp + 32);
                }
            }
        } else {
#pragma unroll
            for (int i = 0; i < WM; i++) {
                const uint4* bp = reinterpret_cast<const uint4*>(WF) + ((gm * WM + i) * KS + ks) * 64 + lane;
                ahc[i] = __ldg(bp); alc[i] = __ldg(bp + 32);
            }
        }
        unsigned koff = (unsigned)ks * 2048;
        constexpr int NP = WN / 2;
        unsigned bh[NP][4], bl[NP][4];
#pragma unroll
        for (int jp = 0; jp < NP; jp++) {
            unsigned col = ((unsigned)((gn * WN + 2 * jp + ntoff) * 16)) ^ swz;
            ldsm_x4_t(baseH + koff + col, bh[jp]);
            ldsm_x4_t(baseL + koff + col, bl[jp]);
        }
#pragma unroll
        for (int jp = 0; jp < NP; jp++)
#pragma unroll
            for (int i = 0; i < WM; i++) {
                mma16816(acc[i][2 * jp],     ahc[i].x, ahc[i].y, ahc[i].z, ahc[i].w, bh[jp][0], bh[jp][1]);
                mma16816(acc[i][2 * jp],     ahc[i].x, ahc[i].y, ahc[i].z, ahc[i].w, bl[jp][0], bl[jp][1]);
                mma16816(acc[i][2 * jp],     alc[i].x, alc[i].y, alc[i].z, alc[i].w, bh[jp][0], bh[jp][1]);
                mma16816(acc[i][2 * jp + 1], ahc[i].x, ahc[i].y, ahc[i].z, ahc[i].w, bh[jp][2], bh[jp][3]);
                mma16816(acc[i][2 * jp + 1], ahc[i].x, ahc[i].y, ahc[i].z, ahc[i].w, bl[jp][2], bl[jp][3]);
                mma16816(acc[i][2 * jp + 1], alc[i].x, alc[i].y, alc[i].z, alc[i].w, bh[jp][2], bh[jp][3]);
            }
        if (PF && ks + 1 < KS) {
#pragma unroll
            for (int i = 0; i < WM; i++) { ahc[i] = ahn[i]; alc[i] = aln[i]; }
        }
    }
    int sl = lane & 15;
#pragma unroll
    for (int i = 0; i < WM; i++) {
        int mrow = (gm * WM + i) * 16 + (sl >> 3) * 8 + (sl & 7);
        unsigned sswz = ((unsigned)(mrow & 7)) << 4;
        unsigned stH = sptr(Dhi) + mrow * 128;
        unsigned stL = sptr(Dlo) + mrow * 128;
#pragma unroll
        for (int j = 0; j < WN; j++) {
            unsigned col = ((unsigned)((gn * WN + j) * 16)) ^ sswz;
            float d0 = acc[i][j][0], d1 = acc[i][j][1], d2 = acc[i][j][2], d3 = acc[i][j][3];
            if (RELU) {
                d0 = fmaxf(d0, 0.f); d1 = fmaxf(d1, 0.f);
                d2 = fmaxf(d2, 0.f); d3 = fmaxf(d3, 0.f);
            }
            unsigned h01, l01, h23, l23;
            split2(d0, d1, h01, l01);
            split2(d2, d3, h23, l23);
            stsm_x2(stH + col, h01, h23);
            stsm_x2(stL + col, l01, l23);
        }
    }
}

// shared layout (bytes): A 256ch x 128B, B 128ch x 128B (hi/lo planes)
constexpr int AHI_OFF = 0;
constexpr int ALO_OFF = 32768;
constexpr int BHI_OFF = 65536;
constexpr int BLO_OFF = 81920;
constexpr int CFL_OFF = 98304;      // 16 KB
constexpr int CL_OFF  = 114688;     // 512 B
constexpr int SMEM_BYTES = 115200;  // 112.5 KiB -> 2 CTAs/SM

// ---------------- kernel A ----------------
__global__ __launch_bounds__(THREADS, 2) void kA(const float* __restrict__ feat,
                                                 const int* __restrict__ clus,
                                                 const float* b_in, const float* b1,
                                                 const float* b2, const float* bc1,
                                                 const float* bc2, const float* bc3) {
    extern __shared__ char sm[];
    __nv_bfloat16* Ahi = (__nv_bfloat16*)(sm + AHI_OFF);
    __nv_bfloat16* Alo = (__nv_bfloat16*)(sm + ALO_OFF);
    __nv_bfloat16* Bhi = (__nv_bfloat16*)(sm + BHI_OFF);
    __nv_bfloat16* Blo = (__nv_bfloat16*)(sm + BLO_OFF);
    int* cfl = (int*)(sm + CFL_OFF);
    int* cl  = (int*)(sm + CL_OFF);
    int t = threadIdx.x, w = t >> 5, lane = t & 31;
    int b = blockIdx.x >> 9, nblk = blockIdx.x & 511;
    int n0 = nblk * P, q0 = nblk * (P / 2);

    for (int r = t; r < CC * 128; r += THREADS) cfl[r] = 0;
    if (t < P) cl[t] = clus[(size_t)b * NN + n0 + t];
    for (int r = t; r < 32 * 32; r += THREADS) {            // features pad 22->32
        int c = r >> 5, q = r & 31;
        float v0 = (c < KIN) ? feat[((size_t)b * NN + n0 + 2 * q) * KIN + c] : 0.0f;
        float v1 = (c < KIN) ? feat[((size_t)b * NN + n0 + 2 * q + 1) * KIN + c] : 0.0f;
        unsigned hw, lw; split2(v0, v1, hw, lw);
        *(unsigned*)((char*)Bhi + soff(c, q)) = hw;
        *(unsigned*)((char*)Blo + soff(c, q)) = lw;
    }
    __syncthreads();
    layerMMA<32, 256, 4, 4, true>(fr_in, b_in, Bhi, Blo, Ahi, Alo, w, lane);
    __syncthreads();
    layerMMA<256, 64, 2, 2, true>(fr_w1[0], b1, Ahi, Alo, Bhi, Blo, w, lane);
    __syncthreads();
    layerMMA<64, 128, 2, 4, true>(fr_w2[0], b2, Bhi, Blo, Ahi, Alo, w, lane);
    __syncthreads();
    for (int r = t; r < 128 * 32; r += THREADS) {           // f2 store + segmax cf
        int c = r >> 5, q = r & 31;
        unsigned h2 = *(unsigned*)((char*)Ahi + soff(c, q));
        unsigned l2 = *(unsigned*)((char*)Alo + soff(c, q));
        size_t gi = ((size_t)(b * 128 + c)) * (NN / 2) + q0 + q;
        g_f2h[gi] = h2; g_f2l[gi] = l2;
        atomicMax(&cfl[cl[2 * q] * 128 + c], __float_as_int(bflo(h2) + bflo(l2)));
        atomicMax(&cfl[cl[2 * q + 1] * 128 + c], __float_as_int(bfhi(h2) + bfhi(l2)));
    }
    layerMMA<128, 128, 2, 4, true>(fr_c1[0], bc1, Ahi, Alo, Bhi, Blo, w, lane);
    __syncthreads();
    layerMMA<128, 256, 4, 4, true>(fr_c2[0], bc2, Bhi, Blo, Ahi, Alo, w, lane);
    __syncthreads();
    layerMMA<256, 32, 1, 2, true>(fr_c3[0], bc3, Ahi, Alo, Bhi, Blo, w, lane);
    __syncthreads();
    for (int r = t; r < 32 * 32; r += THREADS) {            // segmax cc (direct global)
        int c = r >> 5, q = r & 31;
        unsigned h2 = *(unsigned*)((char*)Bhi + soff(c, q));
        unsigned l2 = *(unsigned*)((char*)Blo + soff(c, q));
        float v0 = bflo(h2) + bflo(l2);
        float v1 = bfhi(h2) + bfhi(l2);
        if (v0 > 0.f) atomicMax(&g_cc[(b * CC + cl[2 * q]) * 32 + c], __float_as_int(v0));
        if (v1 > 0.f) atomicMax(&g_cc[(b * CC + cl[2 * q + 1]) * 32 + c], __float_as_int(v1));
    }
    __syncthreads();
    for (int r = t; r < CC * 128; r += THREADS) { int v = cfl[r]; if (v) atomicMax(&g_cf[b * CC * 128 + r], v); }
}

// ---------------- kernel B: per-batch corr matrix + cf @ corr ----------------
__global__ void kB(int it) {
    __shared__ float cm[CC * 32], corr[CC * CC], invn[CC], cfs[CC * 128];
    int b = blockIdx.x, t = threadIdx.x;
    for (int r = t; r < CC * 32; r += TE)  cm[r]  = __int_as_float(g_cc[(it * BB + b) * CC * 32 + r]);
    for (int r = t; r < CC * 128; r += TE) cfs[r] = __int_as_float(g_cf[(it * BB + b) * CC * 128 + r]);
    __syncthreads();
    if (t < CC) {
        float ss = 0.f;
        for (int c = 0; c < 32; c++) { float v = cm[t * 32 + c]; ss += v * v; }
        invn[t] = 1.0f / fmaxf(sqrtf(ss), 1e-12f);
    }
    __syncthreads();
    for (int r = t; r < CC * 32; r += TE) cm[r] *= invn[r >> 5];
    __syncthreads();
    for (int r = t; r < CC * CC; r += TE) {
        int c1 = r >> 5, c2 = r & 31;
        float ss = 0.f;
        for (int c = 0; c < 32; c++) ss += cm[c1 * 32 + c] * cm[c2 * 32 + c];
        corr[r] = ss;
    }
    __syncthreads();
    for (int r = t; r < CC * 128; r += TE) {
        int c2 = r >> 7, ch = r & 127;
        float ss = 0.f;
        for (int c1 = 0; c1 < 32; c1++) ss += cfs[c1 * 128 + ch] * corr[c1 * 32 + c2];
        g_cf2[(it * BB + b) * CC * 128 + r] = ss;
    }
}

// ---------------- kernel C ----------------
__global__ __launch_bounds__(THREADS, 2) void kC(const int* __restrict__ clus,
                                                 const float* b3, const float* b1,
                                                 const float* b2, const float* bc1,
                                                 const float* bc2, const float* bc3) {
    extern __shared__ char sm[];
    __nv_bfloat16* Ahi = (__nv_bfloat16*)(sm + AHI_OFF);
    __nv_bfloat16* Alo = (__nv_bfloat16*)(sm + ALO_OFF);
    __nv_bfloat16* Bhi = (__nv_bfloat16*)(sm + BHI_OFF);
    __nv_bfloat16* Blo = (__nv_bfloat16*)(sm + BLO_OFF);
    int* cfl = (int*)(sm + CFL_OFF);
    int* cl0 = (int*)(sm + CL_OFF);
    int* cl1 = cl0 + 64;
    int t = threadIdx.x, w = t >> 5, lane = t & 31;
    int b = blockIdx.x >> 9, nblk = blockIdx.x & 511;
    int n0 = nblk * P, q0 = nblk * (P / 2);

    for (int r = t; r < CC * 128; r += THREADS) cfl[r] = 0;
    if (t < P) {
        cl0[t] = clus[(size_t)b * NN + n0 + t];
        cl1[t] = clus[(size_t)(BB + b) * NN + n0 + t];
    }
    for (int r = t; r < 128 * 32; r += THREADS) {           // load f2 -> B
        int c = r >> 5, q = r & 31;
        size_t gi = ((size_t)(b * 128 + c)) * (NN / 2) + q0 + q;
        *(unsigned*)((char*)Bhi + soff(c, q)) = g_f2h[gi];
        *(unsigned*)((char*)Blo + soff(c, q)) = g_f2l[gi];
    }
    __syncthreads();
    layerMMA<128, 128, 2, 4, true>(fr_w3[0], b3, Bhi, Blo, Ahi, Alo, w, lane);
    __syncthreads();
    for (int r = t; r < 128 * 32; r += THREADS) {           // pool gather -> A rows 128..255
        int c = r >> 5, q = r & 31;
        float v0 = g_cf2[((size_t)b * CC + cl0[2 * q]) * 128 + c];
        float v1 = g_cf2[((size_t)b * CC + cl0[2 * q + 1]) * 128 + c];
        unsigned hw, lw; split2(v0, v1, hw, lw);
        *(unsigned*)((char*)Ahi + soff(128 + c, q)) = hw;
        *(unsigned*)((char*)Alo + soff(128 + c, q)) = lw;
    }
    __syncthreads();
    layerMMA<256, 64, 2, 2, true>(fr_w1[1], b1, Ahi, Alo, Bhi, Blo, w, lane);
    __syncthreads();
    layerMMA<64, 128, 2, 4, true>(fr_w2[1], b2, Bhi, Blo, Ahi, Alo, w, lane);
    __syncthreads();
    for (int r = t; r < 128 * 32; r += THREADS) {           // f2' store + segmax cf
        int c = r >> 5, q = r & 31;
        unsigned h2 = *(unsigned*)((char*)Ahi + soff(c, q));
        unsigned l2 = *(unsigned*)((char*)Alo + soff(c, q));
        size_t gi = ((size_t)(b * 128 + c)) * (NN / 2) + q0 + q;
        g_f2h[gi] = h2; g_f2l[gi] = l2;
        atomicMax(&cfl[cl1[2 * q] * 128 + c], __float_as_int(bflo(h2) + bflo(l2)));
        atomicMax(&cfl[cl1[2 * q + 1] * 128 + c], __float_as_int(bfhi(h2) + bfhi(l2)));
    }
    layerMMA<128, 128, 2, 4, true>(fr_c1[1], bc1, Ahi, Alo, Bhi, Blo, w, lane);
    __syncthreads();
    layerMMA<128, 256, 4, 4, true>(fr_c2[1], bc2, Bhi, Blo, Ahi, Alo, w, lane);
    __syncthreads();
    layerMMA<256, 32, 1, 2, true>(fr_c3[1], bc3, Ahi, Alo, Bhi, Blo, w, lane);
    __syncthreads();
    for (int r = t; r < 32 * 32; r += THREADS) {            // segmax cc (direct global)
        int c = r >> 5, q = r & 31;
        unsigned h2 = *(unsigned*)((char*)Bhi + soff(c, q));
        unsigned l2 = *(unsigned*)((char*)Blo + soff(c, q));
        float v0 = bflo(h2) + bflo(l2);
        float v1 = bfhi(h2) + bfhi(l2);
        if (v0 > 0.f) atomicMax(&g_cc[((BB + b) * CC + cl1[2 * q]) * 32 + c], __float_as_int(v0));
        if (v1 > 0.f) atomicMax(&g_cc[((BB + b) * CC + cl1[2 * q + 1]) * 32 + c], __float_as_int(v1));
    }
    __syncthreads();
    for (int r = t; r < CC * 128; r += THREADS) { int v = cfl[r]; if (v) atomicMax(&g_cf[(BB + b) * CC * 128 + r], v); }
}

// ---------------- kernel D ----------------
__global__ __launch_bounds__(THREADS, 2) void kD(const int* __restrict__ clus,
                                                 const float* b3, const float* bo1,
                                                 const float* bo2) {
    extern __shared__ char sm[];
    __nv_bfloat16* Ahi = (__nv_bfloat16*)(sm + AHI_OFF);
    __nv_bfloat16* Alo = (__nv_bfloat16*)(sm + ALO_OFF);
    __nv_bfloat16* Bhi = (__nv_bfloat16*)(sm + BHI_OFF);
    __nv_bfloat16* Blo = (__nv_bfloat16*)(sm + BLO_OFF);
    int* cl1 = (int*)(sm + CL_OFF);
    int t = threadIdx.x, w = t >> 5, lane = t & 31;
    int b = blockIdx.x >> 9, nblk = blockIdx.x & 511;
    int n0 = nblk * P, q0 = nblk * (P / 2);

    if (t < P) cl1[t] = clus[(size_t)(BB + b) * NN + n0 + t];
    for (int r = t; r < 128 * 32; r += THREADS) {           // load f2' -> B
        int c = r >> 5, q = r & 31;
        size_t gi = ((size_t)(b * 128 + c)) * (NN / 2) + q0 + q;
        *(unsigned*)((char*)Bhi + soff(c, q)) = g_f2h[gi];
        *(unsigned*)((char*)Blo + soff(c, q)) = g_f2l[gi];
    }
    __syncthreads();
    layerMMA<128, 128, 2, 4, true>(fr_w3[1], b3, Bhi, Blo, Ahi, Alo, w, lane);
    __syncthreads();
    for (int r = t; r < 128 * 32; r += THREADS) {           // pool gather -> A rows 128..255
        int c = r >> 5, q = r & 31;
        float v0 = g_cf2[((size_t)(BB + b) * CC + cl1[2 * q]) * 128 + c];
        float v1 = g_cf2[((size_t)(BB + b) * CC + cl1[2 * q + 1]) * 128 + c];
        unsigned hw, lw; split2(v0, v1, hw, lw);
        *(unsigned*)((char*)Ahi + soff(128 + c, q)) = hw;
        *(unsigned*)((char*)Alo + soff(128 + c, q)) = lw;
    }
    __syncthreads();
    layerMMA<256, 128, 2, 4, true>(fr_o1, bo1, Ahi, Alo, Bhi, Blo, w, lane);
    __syncthreads();
    layerMMA<128, 128, 2, 4, true>(fr_o2, bo2, Bhi, Blo, Ahi, Alo, w, lane);
    __syncthreads();
    if (t < 128) {
        float m = 0.0f;
        for (int q = 0; q < 32; q++) {
            unsigned h2 = *(unsigned*)((char*)Ahi + soff(t, q));
            unsigned l2 = *(unsigned*)((char*)Alo + soff(t, q));
            m = fmaxf(m, fmaxf(bflo(h2) + bflo(l2), bfhi(h2) + bfhi(l2)));
        }
        atomicMax(&g_net[b * 128 + t], __float_as_int(m));
    }
}

// ---------------- kernel E: dense head ----------------
__global__ void kE(const float* __restrict__ dw1, const float* __restrict__ db1,
                   const float* __restrict__ dw2, const float* __restrict__ db2,
                   const float* __restrict__ dw3, const float* __restrict__ db3,
                   float* __restrict__ out) {
    __shared__ float net[BB * 128], l1[BB * 256], l2[BB * 256];
    int t = threadIdx.x;
    for (int r = t; r < BB * 128; r += TE) net[r] = __int_as_float(g_net[r]);
    __syncthreads();
    for (int r = t; r < BB * 256; r += TE) {
        int b = r >> 8, o = r & 255;
        float ss = db1[o];
        for (int i = 0; i < 128; i++) ss = fmaf(net[b * 128 + i], dw1[i * 256 + o], ss);
        l1[r] = ss >= 0.f ? ss : 0.2f * ss;
    }
    __syncthreads();
    for (int r = t; r < BB * 256; r += TE) {
        int b = r >> 8, o = r & 255;
        float ss = db2[o];
        for (int i = 0; i < 256; i++) ss = fmaf(l1[b * 256 + i], dw2[i * 256 + o], ss);
        l2[r] = ss >= 0.f ? ss : 0.2f * ss;
    }
    __syncthreads();
    for (int r = t; r < BB * 40; r += TE) {
        int b = r / 40, o = r % 40;
        float ss = db3[o];
        for (int i = 0; i < 256; i++) ss = fmaf(l2[b * 256 + i], dw3[i * 40 + o], ss);
        out[r] = ss;
    }
}

// ---------------- host launcher ----------------
extern "C" void kernel_launch(void* const* d_in, const int* in_sizes, int n_in,
                              void* d_out, int out_size) {
    const float* feat = (const float*)d_in[0];
    const int*   clus = (const int*)d_in[1];
    const float* w_in = (const float*)d_in[2];
    const float* b_in = (const float*)d_in[3];
    const float* w1   = (const float*)d_in[4];
    const float* b1   = (const float*)d_in[5];
    const float* w2   = (const float*)d_in[6];
    const float* b2   = (const float*)d_in[7];
    const float* w3   = (const float*)d_in[8];
    const float* b3   = (const float*)d_in[9];
    const float* wc1  = (const float*)d_in[10];
    const float* bc1  = (const float*)d_in[11];
    const float* wc2  = (const float*)d_in[12];
    const float* bc2  = (const float*)d_in[13];
    const float* wc3  = (const float*)d_in[14];
    const float* bc3  = (const float*)d_in[15];
    const float* wo1  = (const float*)d_in[16];
    const float* bo1  = (const float*)d_in[17];
    const float* wo2  = (const float*)d_in[18];
    const float* bo2  = (const float*)d_in[19];
    const float* dw1  = (const float*)d_in[20];
    const float* db1  = (const float*)d_in[21];
    const float* dw2  = (const float*)d_in[22];
    const float* db2  = (const float*)d_in[23];
    const float* dw3  = (const float*)d_in[24];
    const float* db3  = (const float*)d_in[25];

    cudaFuncSetAttribute(kA, cudaFuncAttributeMaxDynamicSharedMemorySize, SMEM_BYTES);
    cudaFuncSetAttribute(kC, cudaFuncAttributeMaxDynamicSharedMemorySize, SMEM_BYTES);
    cudaFuncSetAttribute(kD, cudaFuncAttributeMaxDynamicSharedMemorySize, SMEM_BYTES);

    unsigned *p_in, *p_w1, *p_w2, *p_w3, *p_c1, *p_c2, *p_c3, *p_o1, *p_o2;
    cudaGetSymbolAddress((void**)&p_in, fr_in);
    cudaGetSymbolAddress((void**)&p_w1, fr_w1);
    cudaGetSymbolAddress((void**)&p_w2, fr_w2);
    cudaGetSymbolAddress((void**)&p_w3, fr_w3);
    cudaGetSymbolAddress((void**)&p_c1, fr_c1);
    cudaGetSymbolAddress((void**)&p_c2, fr_c2);
    cudaGetSymbolAddress((void**)&p_c3, fr_c3);
    cudaGetSymbolAddress((void**)&p_o1, fr_o1);
    cudaGetSymbolAddress((void**)&p_o2, fr_o2);

    FJobs jobs;
    int idx = 0, total = 0;
    auto add = [&](const float* s, unsigned* d, int Ireal, int Ipad, int O) {
        jobs.src[idx] = s; jobs.dst[idx] = d;
        jobs.Ireal[idx] = Ireal; jobs.Ipad[idx] = Ipad; jobs.O[idx] = O;
        jobs.n[idx] = O * Ipad;
        total += O * Ipad; idx++;
    };
    add(w_in, p_in, KIN, 32, 256);
    for (int it = 0; it < 2; it++) {
        add(w1  + it * 64 * 256,  p_w1 + it * 64 * 256,  256, 256, 64);
        add(w2  + it * 128 * 64,  p_w2 + it * 128 * 64,  64, 64, 128);
        add(w3  + it * 128 * 128, p_w3 + it * 128 * 128, 128, 128, 128);
        add(wc1 + it * 128 * 128, p_c1 + it * 128 * 128, 128, 128, 128);
        add(wc2 + it * 256 * 128, p_c2 + it * 256 * 128, 128, 128, 256);
        add(wc3 + it * 32 * 256,  p_c3 + it * 32 * 256,  256, 256, 32);
    }
    add(wo1, p_o1, 256, 256, 128);
    add(wo2, p_o2, 128, 128, 128);

    // launch order chosen so ncu (-s 5 -c 1) captures kC (6th launch)
    frag_all<<<(total + 255) / 256, 256>>>(jobs, total);  // 1
    zero1_k<<<256, 256>>>();                              // 2
    zero2_k<<<4, 256>>>();                                // 3

    int grid = BB * (NN / P);   // 4096
    kA<<<grid, THREADS, SMEM_BYTES>>>(feat, clus, b_in, b1, b2, bc1, bc2, bc3);   // 4
    kB<<<BB, TE>>>(0);                                                            // 5
    kC<<<grid, THREADS, SMEM_BYTES>>>(clus, b3, b1 + 64, b2 + 128, bc1 + 128, bc2 + 256, bc3 + 32); // 6 <- ncu
    kB<<<BB, TE>>>(1);
    kD<<<grid, THREADS, SMEM_BYTES>>>(clus, b3 + 128, bo1, bo2);
    kE<<<1, TE>>>(dw1, db1, dw2, db2, dw3, db3, (float*)d_out);
}